// round 14
// baseline (speedup 1.0000x reference)
#include <cuda_runtime.h>
#include <cuda_bf16.h>
#include <math.h>
#include <stdint.h>

typedef __nv_bfloat16 bf16;

#define BB   8
#define NN   9216
#define KK   256

// ---------------- scratch -----------------------------------------------------
__device__ bf16  g_tq  [(size_t)BB * 768 * NN];    // rows 0-255: q, 256-767: Eq (unnorm exp)
__device__ bf16  g_skv [(size_t)BB * 1024 * NN];   // rows 0-511: kv, 512-1023: Ek
__device__ bf16  g_srcb[(size_t)BB * 256 * NN];
__device__ bf16  g_tgtb[(size_t)BB * 256 * NN];
__device__ bf16  g_Wtgt[768 * 256];
__device__ bf16  g_Wsrc[1024 * 256];
__device__ float g_btgt[768];
__device__ float g_bsrc[1024];
__device__ float g_Sq  [(size_t)BB * NN];          // column sums -> inverted
__device__ float g_Sk  [(size_t)BB * NN];
__device__ bf16  g_U   [(size_t)BB * 256 * 512];
__device__ float g_qr  [64 * 32 * 64];
__device__ float g_krvr[64 * 64 * 64];
__device__ float g_vals[64 * 2048];

// ---------------- prep: zeros + conversions + weight/bias concat --------------
#define C_SRC  4718592
#define C_TGT  4718592
#define C_WQ   16384
#define C_WKV  32768
#define C_WR   32768
#define C_ZTOT 135168   // qr 32768 + krvr 65536 + Sq 18432 + Sk 18432 (float4 units)
#define C_BQ   64
#define C_BRQ  128
#define C_BKV  128
#define C_BRK  128
__global__ __launch_bounds__(256) void prep_k(
    const float* __restrict__ src, const float* __restrict__ tgt,
    const float* __restrict__ Wq, const float* __restrict__ Wkv,
    const float* __restrict__ Wrq, const float* __restrict__ Wrk,
    const float* __restrict__ bq, const float* __restrict__ bkv,
    const float* __restrict__ brq, const float* __restrict__ brk,
    bf16* srcb, bf16* tgtb, bf16* wtgt, bf16* wsrc,
    float* btgt, float* bsrc, float* qr, float* krvr, float* Sq, float* Sk)
{
    long long i = (long long)blockIdx.x * 256 + threadIdx.x;
    const float* s; bf16* d; long long o;
    if (i < C_SRC)                 { s = src; d = srcb; o = i; }
    else if ((i -= C_SRC) < C_TGT) { s = tgt; d = tgtb; o = i; }
    else if ((i -= C_TGT) < C_WQ)  { s = Wq;  d = wtgt; o = i; }
    else if ((i -= C_WQ) < C_WR)   { s = Wrq; d = wtgt + 65536; o = i; }
    else if ((i -= C_WR) < C_WKV)  { s = Wkv; d = wsrc; o = i; }
    else if ((i -= C_WKV) < C_WR)  { s = Wrk; d = wsrc + 131072; o = i; }
    else if ((i -= C_WR) < C_ZTOT) {
        float4 z = {0.f, 0.f, 0.f, 0.f};
        if (i < 32768)       *(float4*)(qr + i * 4) = z;
        else if (i < 98304)  *(float4*)(krvr + (i - 32768) * 4) = z;
        else if (i < 116736) *(float4*)(Sq + (i - 98304) * 4) = z;
        else                 *(float4*)(Sk + (i - 116736) * 4) = z;
        return;
    }
    else if ((i -= C_ZTOT) < C_BQ) { *(float4*)(btgt + i * 4)       = *(const float4*)(bq  + i * 4); return; }
    else if ((i -= C_BQ) < C_BRQ)  { *(float4*)(btgt + 256 + i * 4) = *(const float4*)(brq + i * 4); return; }
    else if ((i -= C_BRQ) < C_BKV) { *(float4*)(bsrc + i * 4)       = *(const float4*)(bkv + i * 4); return; }
    else if ((i -= C_BKV) < C_BRK) { *(float4*)(bsrc + 512 + i * 4) = *(const float4*)(brk + i * 4); return; }
    else return;
    float4 v = *(const float4*)(s + o * 4);
    __nv_bfloat162 h0 = { __float2bfloat16(v.x), __float2bfloat16(v.y) };
    __nv_bfloat162 h1 = { __float2bfloat16(v.z), __float2bfloat16(v.w) };
    *(__nv_bfloat162*)(d + o * 4)     = h0;
    *(__nv_bfloat162*)(d + o * 4 + 2) = h1;
}
#define PREP_TOTAL ((long long)C_SRC + C_TGT + C_WQ + C_WR + C_WKV + C_WR + C_ZTOT + C_BQ + C_BRQ + C_BKV + C_BRK)

// ---------------- invert column sums ------------------------------------------
__global__ __launch_bounds__(256) void inv_k(float* Sq, float* Sk) {
    int i = blockIdx.x * 256 + threadIdx.x;
    if (i < BB * NN) { Sq[i] = 1.f / Sq[i]; Sk[i] = 1.f / Sk[i]; }
}

// ---------------- PTX helpers -------------------------------------------------
__device__ __forceinline__ uint32_t s2u(const void* p) {
    return (uint32_t)__cvta_generic_to_shared(p);
}
__device__ __forceinline__ void ldsm4(uint32_t& r0, uint32_t& r1, uint32_t& r2,
                                      uint32_t& r3, uint32_t a) {
    asm volatile("ldmatrix.sync.aligned.m8n8.x4.shared.b16 {%0,%1,%2,%3},[%4];\n"
        : "=r"(r0), "=r"(r1), "=r"(r2), "=r"(r3) : "r"(a));
}
__device__ __forceinline__ void ldsm4t(uint32_t& r0, uint32_t& r1, uint32_t& r2,
                                       uint32_t& r3, uint32_t a) {
    asm volatile("ldmatrix.sync.aligned.m8n8.x4.trans.shared.b16 {%0,%1,%2,%3},[%4];\n"
        : "=r"(r0), "=r"(r1), "=r"(r2), "=r"(r3) : "r"(a));
}
__device__ __forceinline__ void ldsm2(uint32_t& r0, uint32_t& r1, uint32_t a) {
    asm volatile("ldmatrix.sync.aligned.m8n8.x2.shared.b16 {%0,%1},[%2];\n"
        : "=r"(r0), "=r"(r1) : "r"(a));
}
__device__ __forceinline__ void mma16816(float* c, const uint32_t* a,
                                         uint32_t b0, uint32_t b1) {
    asm volatile(
        "mma.sync.aligned.m16n8k16.row.col.f32.bf16.bf16.f32 "
        "{%0,%1,%2,%3},{%4,%5,%6,%7},{%8,%9},{%0,%1,%2,%3};\n"
        : "+f"(c[0]), "+f"(c[1]), "+f"(c[2]), "+f"(c[3])
        : "r"(a[0]), "r"(a[1]), "r"(a[2]), "r"(a[3]), "r"(b0), "r"(b1));
}
__device__ __forceinline__ void cpasync16(uint32_t s, const void* g) {
    asm volatile("cp.async.cg.shared.global [%0], [%1], 16;\n" :: "r"(s), "l"(g));
}
__device__ __forceinline__ void cp_commit() { asm volatile("cp.async.commit_group;\n"); }
__device__ __forceinline__ void cp_wait0()  { asm volatile("cp.async.wait_group 0;\n"); }
__device__ __forceinline__ void cp_wait1()  { asm volatile("cp.async.wait_group 1;\n"); }

// ---------------- bf16 HMMA GEMM, 128x128 tile, 4 warps @ 64x64, BK=64 --------
// mode 0: write bf16; rows >= expFrom write exp(acc+bias) and atomic col-sums.
// mode 1: Yf = tgt + alpha*(acc*invS[n] + bias)
#define APAD 72
#define BPAD 136
#define SA_ELEMS (128 * APAD)
#define SB_ELEMS (64 * BPAD)
#define NSTAGE 3
#define HSMEM_BYTES (NSTAGE * (SA_ELEMS + SB_ELEMS) * 2)   // 107520

__global__ __launch_bounds__(128, 2) void hgemm_k(
    const bf16* __restrict__ Ab, const float* __restrict__ bias,
    const bf16* __restrict__ Xb, int xstride,
    bf16* __restrict__ Yb, float* __restrict__ Yf,
    int M, int K, int abatch, int mode, int expFrom, float* __restrict__ Scol,
    const float* __restrict__ tgt, const float* __restrict__ alphap)
{
    extern __shared__ bf16 sm[];
    bf16* sA = sm;
    bf16* sB = sm + NSTAGE * SA_ELEMS;

    const int tid  = threadIdx.x;
    const int warp = tid >> 5, lane = tid & 31;
    const int wm   = warp >> 1, wn = warp & 1;
    const int n0   = blockIdx.x * 128;
    const int m0   = blockIdx.y * 128;
    const int b    = blockIdx.z;
    const bf16* X  = Xb + (size_t)b * xstride * NN;
    const bf16* A  = Ab + (abatch ? (size_t)b * M * K : 0);
    const int KT   = K >> 6;

    float acc[4][8][4];
    #pragma unroll
    for (int i = 0; i < 4; i++)
        #pragma unroll
        for (int j = 0; j < 8; j++)
            #pragma unroll
            for (int k = 0; k < 4; k++) acc[i][j][k] = 0.f;

    auto issue_tile = [&](int kt, int buf) {
        bf16* a  = sA + buf * SA_ELEMS;
        bf16* bb = sB + buf * SB_ELEMS;
        #pragma unroll
        for (int i = 0; i < 8; i++) {
            int c = tid + i * 128;
            int r = c >> 3, k = (c & 7) * 8;
            cpasync16(s2u(&a[r * APAD + k]), A + (size_t)(m0 + r) * K + kt * 64 + k);
        }
        #pragma unroll
        for (int i = 0; i < 8; i++) {
            int c = tid + i * 128;
            int r = c >> 4, cc = (c & 15) * 8;
            cpasync16(s2u(&bb[r * BPAD + cc]), X + (size_t)(kt * 64 + r) * NN + n0 + cc);
        }
        cp_commit();
    };

    issue_tile(0, 0);
    if (KT > 1) issue_tile(1, 1);
    cp_wait1();
    __syncthreads();

    for (int kt = 0; kt < KT; kt++) {
        int cur = kt % NSTAGE;
        bf16* a  = sA + cur * SA_ELEMS;
        bf16* bb = sB + cur * SB_ELEMS;

        #pragma unroll
        for (int ks = 0; ks < 4; ks++) {
            uint32_t af[4][4];
            #pragma unroll
            for (int mt = 0; mt < 4; mt++) {
                int row = wm * 64 + mt * 16 + (lane & 15);
                int col = ks * 16 + (lane >> 4) * 8;
                ldsm4(af[mt][0], af[mt][1], af[mt][2], af[mt][3],
                      s2u(&a[row * APAD + col]));
            }
            uint32_t bfr[4][4];
            #pragma unroll
            for (int ntg = 0; ntg < 4; ntg++) {
                int row = ks * 16 + (lane & 15);
                int col = wn * 64 + ntg * 16 + (lane >> 4) * 8;
                ldsm4t(bfr[ntg][0], bfr[ntg][1], bfr[ntg][2], bfr[ntg][3],
                       s2u(&bb[row * BPAD + col]));
            }
            #pragma unroll
            for (int mt = 0; mt < 4; mt++)
                #pragma unroll
                for (int nt = 0; nt < 8; nt++) {
                    int ntg = nt >> 1, half = nt & 1;
                    mma16816(acc[mt][nt], af[mt],
                             bfr[ntg][half * 2], bfr[ntg][half * 2 + 1]);
                }
        }

        if (kt + 2 < KT) {
            issue_tile(kt + 2, (kt + 2) % NSTAGE);
            cp_wait1();
            __syncthreads();
        } else if (kt + 1 < KT) {
            cp_wait0();
            __syncthreads();
        }
    }

    const bool doExp = (mode == 0) && (expFrom >= 0) && (m0 >= expFrom);
    float* colsum = (float*)sm;           // reuse pipeline smem in epilogue
    if (doExp) {
        __syncthreads();                  // all warps done reading smem
        if (tid < 128) colsum[tid] = 0.f;
        __syncthreads();
    }

    float al = (mode == 1) ? *alphap : 0.f;
    #pragma unroll
    for (int mt = 0; mt < 4; mt++) {
        #pragma unroll
        for (int rr = 0; rr < 2; rr++) {
            int m = m0 + wm * 64 + mt * 16 + rr * 8 + (lane >> 2);
            float bi = bias[m];
            size_t ybase = ((size_t)b * M + m) * NN + n0;
            #pragma unroll
            for (int nt = 0; nt < 8; nt++) {
                int n = wn * 64 + nt * 8 + (lane & 3) * 2;
                float c0 = acc[mt][nt][rr * 2 + 0] + bi;
                float c1 = acc[mt][nt][rr * 2 + 1] + bi;
                if (mode == 0) {
                    if (doExp) { c0 = __expf(c0); c1 = __expf(c1); }
                    __nv_bfloat162 o = { __float2bfloat16(c0), __float2bfloat16(c1) };
                    *(__nv_bfloat162*)(Yb + ybase + n) = o;
                    if (doExp) {
                        atomicAdd(&colsum[n],     __bfloat162float(o.x));
                        atomicAdd(&colsum[n + 1], __bfloat162float(o.y));
                    }
                } else {
                    float2 iv = *(const float2*)(Scol + (size_t)b * NN + n0 + n);
                    size_t tbase = ((size_t)b * 256 + m) * NN + n0;
                    float2 t = *(const float2*)(tgt + tbase + n);
                    float2 o = { t.x + al * (c0 * iv.x - bi + bi),   // keep simple:
                                 0.f };
                    o.x = t.x + al * ((c0 - bi) * iv.x + bi);
                    o.y = t.y + al * ((c1 - bi) * iv.y + bi);
                    *(float2*)(Yf + ybase + n) = o;
                }
            }
        }
    }

    if (doExp) {
        __syncthreads();
        if (tid < 128)
            atomicAdd(&Scol[(size_t)b * NN + n0 + tid], colsum[tid]);
    }
}

// ---------------- tensor-core outer reduce (R scaled by invS) -----------------
template<int MR>
__global__ __launch_bounds__(256) void outer_mma_k(
    const bf16* __restrict__ A, int aStride, int aH,
    const bf16* __restrict__ Rm, int rStride, int rOff,
    const float* __restrict__ invSb, float* __restrict__ out)
{
    constexpr int AROWS = MR * 16;
    __shared__ bf16 sA[AROWS * 72];
    __shared__ bf16 sR[64 * 72];
    int bh = blockIdx.x, b = bh >> 3, h = bh & 7;
    const bf16* Ab = A  + ((size_t)b * aStride + h * aH) * NN;
    const bf16* Rb = Rm + ((size_t)b * rStride + rOff + h * 64) * NN;
    const float* iS = invSb + (size_t)b * NN;
    float* ob = out + (size_t)bh * (AROWS * 64);
    int tid = threadIdx.x, warp = tid >> 5, lane = tid & 31;

    float acc[MR][4];
    #pragma unroll
    for (int i = 0; i < MR; i++)
        #pragma unroll
        for (int j = 0; j < 4; j++) acc[i][j] = 0.f;

    int kbase = blockIdx.y * 1024;
    for (int kb = 0; kb < 16; kb++) {
        int k0 = kbase + kb * 64;
        #pragma unroll
        for (int c = tid; c < AROWS * 8; c += 256) {
            int r = c >> 3, cc = (c & 7) * 8;
            cpasync16(s2u(&sA[r * 72 + cc]), Ab + (size_t)r * NN + k0 + cc);
        }
        cp_commit();
        // R: LDG E (bf16) * invS -> STS
        #pragma unroll
        for (int c = tid; c < 512; c += 256) {
            int r = c >> 3, cc = (c & 7) * 8;
            uint4 ev = *(const uint4*)(Rb + (size_t)r * NN + k0 + cc);
            float4 s0 = *(const float4*)(iS + k0 + cc);
            float4 s1 = *(const float4*)(iS + k0 + cc + 4);
            __nv_bfloat162* ep = (__nv_bfloat162*)&ev;
            __nv_bfloat162 o[4];
            float2 f0 = __bfloat1622float2(ep[0]);
            float2 f1 = __bfloat1622float2(ep[1]);
            float2 f2 = __bfloat1622float2(ep[2]);
            float2 f3 = __bfloat1622float2(ep[3]);
            o[0] = __floats2bfloat162_rn(f0.x * s0.x, f0.y * s0.y);
            o[1] = __floats2bfloat162_rn(f1.x * s0.z, f1.y * s0.w);
            o[2] = __floats2bfloat162_rn(f2.x * s1.x, f2.y * s1.y);
            o[3] = __floats2bfloat162_rn(f3.x * s1.z, f3.y * s1.w);
            *(uint4*)&sR[r * 72 + cc] = *(uint4*)o;
        }
        cp_wait0();
        __syncthreads();

        int r0 = warp * 8;
        #pragma unroll
        for (int ks = 0; ks < 4; ks++) {
            uint32_t a[MR][4];
            #pragma unroll
            for (int mt = 0; mt < MR; mt++)
                ldsm4(a[mt][0], a[mt][1], a[mt][2], a[mt][3],
                      s2u(&sA[(mt * 16 + (lane & 15)) * 72 + ks * 16 + (lane >> 4) * 8]));
            uint32_t b0, b1;
            {
                int j = lane & 7, half = (lane >> 3) & 1;
                ldsm2(b0, b1, s2u(&sR[(r0 + j) * 72 + ks * 16 + half * 8]));
            }
            #pragma unroll
            for (int mt = 0; mt < MR; mt++)
                mma16816(acc[mt], a[mt], b0, b1);
        }
        __syncthreads();
    }

    int row = lane >> 2, col = warp * 8 + (lane & 3) * 2;
    #pragma unroll
    for (int mt = 0; mt < MR; mt++) {
        atomicAdd(&ob[(mt * 16 + row)     * 64 + col],     acc[mt][0]);
        atomicAdd(&ob[(mt * 16 + row)     * 64 + col + 1], acc[mt][1]);
        atomicAdd(&ob[(mt * 16 + row + 8) * 64 + col],     acc[mt][2]);
        atomicAdd(&ob[(mt * 16 + row + 8) * 64 + col + 1], acc[mt][3]);
    }
}

// ---------------- tiny attention per (b,h) ------------------------------------
__global__ __launch_bounds__(64) void attn_k(
    const float* __restrict__ qr, const float* __restrict__ krvr,
    float* __restrict__ vals)
{
    int bh = blockIdx.x; int t = threadIdx.x;
    __shared__ float sq[2048], sk[2048], sv[2048];
    const float* pq = qr   + (size_t)bh * 2048;
    const float* pk = krvr + (size_t)bh * 4096;
    const float* pv = pk + 2048;
    for (int i = t; i < 2048; i += 64) { sq[i] = pq[i]; sk[i] = pk[i]; sv[i] = pv[i]; }
    __syncthreads();

    float sc[64];
    #pragma unroll 4
    for (int k = 0; k < 64; k++) {
        float s = 0.f;
        #pragma unroll
        for (int d = 0; d < 32; d++) s += sq[d * 64 + t] * sk[d * 64 + k];
        sc[k] = s * 0.17677669529663687f;
    }
    float m = -1e30f;
    #pragma unroll
    for (int k = 0; k < 64; k++) m = fmaxf(m, sc[k]);
    float s = 0.f;
    #pragma unroll
    for (int k = 0; k < 64; k++) { sc[k] = __expf(sc[k] - m); s += sc[k]; }
    float inv = 1.f / s;
    #pragma unroll
    for (int k = 0; k < 64; k++) sc[k] *= inv;

    #pragma unroll 4
    for (int d = 0; d < 32; d++) {
        float v = 0.f;
        #pragma unroll
        for (int k = 0; k < 64; k++) v += sv[d * 64 + k] * sc[k];
        vals[(size_t)bh * 2048 + d * 64 + t] = v;
    }
}

// ---------------- U[b][m][h*64+r] = sum_d Wout[m][h*32+d] * vals[bh][d][r] ----
__global__ __launch_bounds__(256) void u_k(
    const float* __restrict__ Wout, const float* __restrict__ vals,
    bf16* __restrict__ U)
{
    int bh = blockIdx.x, b = bh >> 3, h = bh & 7;
    int m = threadIdx.x;
    __shared__ float vs[2048];
    const float* pv = vals + (size_t)bh * 2048;
    for (int i = threadIdx.x; i < 2048; i += 256) vs[i] = pv[i];
    __syncthreads();

    float acc[64];
    #pragma unroll
    for (int r = 0; r < 64; r++) acc[r] = 0.f;
    #pragma unroll 4
    for (int d = 0; d < 32; d++) {
        float w = Wout[(size_t)m * 256 + h * 32 + d];
        #pragma unroll
        for (int r = 0; r < 64; r++) acc[r] += w * vs[d * 64 + r];
    }
    bf16* up = U + ((size_t)b * 256 + m) * 512 + h * 64;
    #pragma unroll
    for (int r = 0; r < 32; r++) {
        __nv_bfloat162 o = { __float2bfloat16(acc[r * 2]), __float2bfloat16(acc[r * 2 + 1]) };
        *(__nv_bfloat162*)(up + r * 2) = o;
    }
}

// ------------------------------ launcher --------------------------------------
extern "C" void kernel_launch(void* const* d_in, const int* in_sizes, int n_in,
                              void* d_out, int out_size)
{
    const float* src   = (const float*)d_in[0];
    const float* tgt   = (const float*)d_in[1];
    const float* Wq    = (const float*)d_in[2];
    const float* bq    = (const float*)d_in[3];
    const float* Wkv   = (const float*)d_in[4];
    const float* bkv   = (const float*)d_in[5];
    const float* Wrq   = (const float*)d_in[6];
    const float* brq   = (const float*)d_in[7];
    const float* Wrk   = (const float*)d_in[8];
    const float* brk   = (const float*)d_in[9];
    const float* Wout  = (const float*)d_in[10];
    const float* bout  = (const float*)d_in[11];
    const float* alpha = (const float*)d_in[12];
    float* out = (float*)d_out;

    bf16 *ptq, *pskv, *psrcb, *ptgtb, *pWtgt, *pWsrc, *pU;
    float *pbtgt, *pbsrc, *pSq, *pSk, *pqr, *pkrvr, *pvals;
    cudaGetSymbolAddress((void**)&ptq,   g_tq);
    cudaGetSymbolAddress((void**)&pskv,  g_skv);
    cudaGetSymbolAddress((void**)&psrcb, g_srcb);
    cudaGetSymbolAddress((void**)&ptgtb, g_tgtb);
    cudaGetSymbolAddress((void**)&pWtgt, g_Wtgt);
    cudaGetSymbolAddress((void**)&pWsrc, g_Wsrc);
    cudaGetSymbolAddress((void**)&pbtgt, g_btgt);
    cudaGetSymbolAddress((void**)&pbsrc, g_bsrc);
    cudaGetSymbolAddress((void**)&pSq,   g_Sq);
    cudaGetSymbolAddress((void**)&pSk,   g_Sk);
    cudaGetSymbolAddress((void**)&pU,    g_U);
    cudaGetSymbolAddress((void**)&pqr,   g_qr);
    cudaGetSymbolAddress((void**)&pkrvr, g_krvr);
    cudaGetSymbolAddress((void**)&pvals, g_vals);

    cudaFuncSetAttribute(hgemm_k, cudaFuncAttributeMaxDynamicSharedMemorySize, HSMEM_BYTES);

    {
        int blocks = (int)((PREP_TOTAL + 255) / 256);
        prep_k<<<blocks, 256>>>(src, tgt, Wq, Wkv, Wrq, Wrk, bq, bkv, brq, brk,
                                psrcb, ptgtb, pWtgt, pWsrc, pbtgt, pbsrc,
                                pqr, pkrvr, pSq, pSk);
    }

    // fused projections; Rk/Rq rows write exp + column sums
    hgemm_k<<<dim3(NN / 128, 8, BB), 128, HSMEM_BYTES>>>(
        pWsrc, pbsrc, psrcb, 256, pskv, nullptr, 1024, 256, 0, 0, 512, pSk, nullptr, nullptr);
    hgemm_k<<<dim3(NN / 128, 6, BB), 128, HSMEM_BYTES>>>(
        pWtgt, pbtgt, ptgtb, 256, ptq, nullptr, 768, 256, 0, 0, 256, pSq, nullptr, nullptr);

    inv_k<<<(BB * NN + 255) / 256, 256>>>(pSq, pSk);

    outer_mma_k<2><<<dim3(64, 9), 256>>>(ptq,  768,  32, ptq,  768,  256, pSq, pqr);
    outer_mma_k<4><<<dim3(64, 9), 256>>>(pskv, 1024, 64, pskv, 1024, 512, pSk, pkrvr);

    attn_k<<<64, 64>>>(pqr, pkrvr, pvals);

    u_k<<<64, 256>>>(Wout, pvals, pU);

    // out = tgt + alpha * ((U @ Eq) * invSq + bout)
    hgemm_k<<<dim3(NN / 128, 2, BB), 128, HSMEM_BYTES>>>(
        pU, bout, ptq + (size_t)256 * NN, 768, nullptr, out, 256, 512, 1, 1, -1, pSq, tgt, alpha);
}

// round 15
// speedup vs baseline: 2.4849x; 2.4849x over previous
#include <cuda_runtime.h>
#include <cuda_bf16.h>
#include <math.h>
#include <stdint.h>

typedef __nv_bfloat16 bf16;

#define BB   8
#define NN   9216
#define KK   256

// ---------------- scratch -----------------------------------------------------
__device__ bf16  g_tq  [(size_t)BB * 768 * NN];    // rows 0-255: q, 256-767: Rq (normalized)
__device__ bf16  g_skv [(size_t)BB * 1024 * NN];   // rows 0-511: kv, 512-1023: Rk RAW scores
__device__ bf16  g_srcb[(size_t)BB * 256 * NN];
__device__ bf16  g_tgtb[(size_t)BB * 256 * NN];
__device__ bf16  g_Wtgt[768 * 256];
__device__ bf16  g_Wsrc[1024 * 256];
__device__ float g_btgt[768];
__device__ float g_bsrc[1024];
__device__ float g_iSk [(size_t)BB * NN];          // 1 / sum_c exp(Rk raw)
__device__ bf16  g_U   [(size_t)BB * 256 * 512];
__device__ float g_qr  [64 * 32 * 64];
__device__ float g_krvr[64 * 64 * 64];
__device__ float g_vals[64 * 2048];

// ---------------- prep: zeros + conversions + weight/bias concat --------------
#define C_SRC  4718592
#define C_TGT  4718592
#define C_WQ   16384
#define C_WKV  32768
#define C_WR   32768
#define C_Z    98304
#define C_BQ   64
#define C_BRQ  128
#define C_BKV  128
#define C_BRK  128
__global__ __launch_bounds__(256) void prep_k(
    const float* __restrict__ src, const float* __restrict__ tgt,
    const float* __restrict__ Wq, const float* __restrict__ Wkv,
    const float* __restrict__ Wrq, const float* __restrict__ Wrk,
    const float* __restrict__ bq, const float* __restrict__ bkv,
    const float* __restrict__ brq, const float* __restrict__ brk,
    bf16* srcb, bf16* tgtb, bf16* wtgt, bf16* wsrc,
    float* btgt, float* bsrc, float* qr, float* krvr)
{
    long long i = (long long)blockIdx.x * 256 + threadIdx.x;
    const float* s; bf16* d; long long o;
    if (i < C_SRC)                 { s = src; d = srcb; o = i; }
    else if ((i -= C_SRC) < C_TGT) { s = tgt; d = tgtb; o = i; }
    else if ((i -= C_TGT) < C_WQ)  { s = Wq;  d = wtgt; o = i; }
    else if ((i -= C_WQ) < C_WR)   { s = Wrq; d = wtgt + 65536; o = i; }
    else if ((i -= C_WR) < C_WKV)  { s = Wkv; d = wsrc; o = i; }
    else if ((i -= C_WKV) < C_WR)  { s = Wrk; d = wsrc + 131072; o = i; }
    else if ((i -= C_WR) < C_Z) {
        float4 z = {0.f, 0.f, 0.f, 0.f};
        if (i < 32768) *(float4*)(qr + i * 4) = z;
        else           *(float4*)(krvr + (i - 32768) * 4) = z;
        return;
    }
    else if ((i -= C_Z) < C_BQ)  { *(float4*)(btgt + i * 4)       = *(const float4*)(bq  + i * 4); return; }
    else if ((i -= C_BQ) < C_BRQ){ *(float4*)(btgt + 256 + i * 4) = *(const float4*)(brq + i * 4); return; }
    else if ((i -= C_BRQ) < C_BKV){ *(float4*)(bsrc + i * 4)      = *(const float4*)(bkv + i * 4); return; }
    else if ((i -= C_BKV) < C_BRK){ *(float4*)(bsrc + 512 + i * 4)= *(const float4*)(brk + i * 4); return; }
    else return;
    float4 v = *(const float4*)(s + o * 4);
    __nv_bfloat162 h0 = { __float2bfloat16(v.x), __float2bfloat16(v.y) };
    __nv_bfloat162 h1 = { __float2bfloat16(v.z), __float2bfloat16(v.w) };
    *(__nv_bfloat162*)(d + o * 4)     = h0;
    *(__nv_bfloat162*)(d + o * 4 + 2) = h1;
}
#define PREP_TOTAL ((long long)C_SRC + C_TGT + C_WQ + C_WR + C_WKV + C_WR + C_Z + C_BQ + C_BRQ + C_BKV + C_BRK)

// ---------------- PTX helpers -------------------------------------------------
__device__ __forceinline__ uint32_t s2u(const void* p) {
    return (uint32_t)__cvta_generic_to_shared(p);
}
__device__ __forceinline__ void ldsm4(uint32_t& r0, uint32_t& r1, uint32_t& r2,
                                      uint32_t& r3, uint32_t a) {
    asm volatile("ldmatrix.sync.aligned.m8n8.x4.shared.b16 {%0,%1,%2,%3},[%4];\n"
        : "=r"(r0), "=r"(r1), "=r"(r2), "=r"(r3) : "r"(a));
}
__device__ __forceinline__ void ldsm4t(uint32_t& r0, uint32_t& r1, uint32_t& r2,
                                       uint32_t& r3, uint32_t a) {
    asm volatile("ldmatrix.sync.aligned.m8n8.x4.trans.shared.b16 {%0,%1,%2,%3},[%4];\n"
        : "=r"(r0), "=r"(r1), "=r"(r2), "=r"(r3) : "r"(a));
}
__device__ __forceinline__ void ldsm2(uint32_t& r0, uint32_t& r1, uint32_t a) {
    asm volatile("ldmatrix.sync.aligned.m8n8.x2.shared.b16 {%0,%1},[%2];\n"
        : "=r"(r0), "=r"(r1) : "r"(a));
}
__device__ __forceinline__ void mma16816(float* c, const uint32_t* a,
                                         uint32_t b0, uint32_t b1) {
    asm volatile(
        "mma.sync.aligned.m16n8k16.row.col.f32.bf16.bf16.f32 "
        "{%0,%1,%2,%3},{%4,%5,%6,%7},{%8,%9},{%0,%1,%2,%3};\n"
        : "+f"(c[0]), "+f"(c[1]), "+f"(c[2]), "+f"(c[3])
        : "r"(a[0]), "r"(a[1]), "r"(a[2]), "r"(a[3]), "r"(b0), "r"(b1));
}
__device__ __forceinline__ void cpasync16(uint32_t s, const void* g) {
    asm volatile("cp.async.cg.shared.global [%0], [%1], 16;\n" :: "r"(s), "l"(g));
}
__device__ __forceinline__ void cp_commit() { asm volatile("cp.async.commit_group;\n"); }
__device__ __forceinline__ void cp_wait0()  { asm volatile("cp.async.wait_group 0;\n"); }
__device__ __forceinline__ void cp_wait1()  { asm volatile("cp.async.wait_group 1;\n"); }

// ---------------- bf16 HMMA GEMM (FROZEN: byte-identical to R13) --------------
#define APAD 72
#define BPAD 136
#define SA_ELEMS (128 * APAD)
#define SB_ELEMS (64 * BPAD)
#define NSTAGE 3
#define HSMEM_BYTES (NSTAGE * (SA_ELEMS + SB_ELEMS) * 2)   // 107520

__global__ __launch_bounds__(128, 2) void hgemm_k(
    const bf16* __restrict__ Ab, const float* __restrict__ bias,
    const bf16* __restrict__ Xb, int xstride,
    bf16* __restrict__ Yb, float* __restrict__ Yf,
    int M, int K, int abatch, int mode,
    const float* __restrict__ tgt, const float* __restrict__ alphap)
{
    extern __shared__ bf16 sm[];
    bf16* sA = sm;
    bf16* sB = sm + NSTAGE * SA_ELEMS;

    const int tid  = threadIdx.x;
    const int warp = tid >> 5, lane = tid & 31;
    const int wm   = warp >> 1, wn = warp & 1;
    const int n0   = blockIdx.x * 128;
    const int m0   = blockIdx.y * 128;
    const int b    = blockIdx.z;
    const bf16* X  = Xb + (size_t)b * xstride * NN;
    const bf16* A  = Ab + (abatch ? (size_t)b * M * K : 0);
    const int KT   = K >> 6;

    float acc[4][8][4];
    #pragma unroll
    for (int i = 0; i < 4; i++)
        #pragma unroll
        for (int j = 0; j < 8; j++)
            #pragma unroll
            for (int k = 0; k < 4; k++) acc[i][j][k] = 0.f;

    auto issue_tile = [&](int kt, int buf) {
        bf16* a  = sA + buf * SA_ELEMS;
        bf16* bb = sB + buf * SB_ELEMS;
        #pragma unroll
        for (int i = 0; i < 8; i++) {
            int c = tid + i * 128;
            int r = c >> 3, k = (c & 7) * 8;
            cpasync16(s2u(&a[r * APAD + k]), A + (size_t)(m0 + r) * K + kt * 64 + k);
        }
        #pragma unroll
        for (int i = 0; i < 8; i++) {
            int c = tid + i * 128;
            int r = c >> 4, cc = (c & 15) * 8;
            cpasync16(s2u(&bb[r * BPAD + cc]), X + (size_t)(kt * 64 + r) * NN + n0 + cc);
        }
        cp_commit();
    };

    issue_tile(0, 0);
    if (KT > 1) issue_tile(1, 1);
    cp_wait1();
    __syncthreads();

    for (int kt = 0; kt < KT; kt++) {
        int cur = kt % NSTAGE;
        bf16* a  = sA + cur * SA_ELEMS;
        bf16* bb = sB + cur * SB_ELEMS;

        #pragma unroll
        for (int ks = 0; ks < 4; ks++) {
            uint32_t af[4][4];
            #pragma unroll
            for (int mt = 0; mt < 4; mt++) {
                int row = wm * 64 + mt * 16 + (lane & 15);
                int col = ks * 16 + (lane >> 4) * 8;
                ldsm4(af[mt][0], af[mt][1], af[mt][2], af[mt][3],
                      s2u(&a[row * APAD + col]));
            }
            uint32_t bfr[4][4];
            #pragma unroll
            for (int ntg = 0; ntg < 4; ntg++) {
                int row = ks * 16 + (lane & 15);
                int col = wn * 64 + ntg * 16 + (lane >> 4) * 8;
                ldsm4t(bfr[ntg][0], bfr[ntg][1], bfr[ntg][2], bfr[ntg][3],
                       s2u(&bb[row * BPAD + col]));
            }
            #pragma unroll
            for (int mt = 0; mt < 4; mt++)
                #pragma unroll
                for (int nt = 0; nt < 8; nt++) {
                    int ntg = nt >> 1, half = nt & 1;
                    mma16816(acc[mt][nt], af[mt],
                             bfr[ntg][half * 2], bfr[ntg][half * 2 + 1]);
                }
        }

        if (kt + 2 < KT) {
            issue_tile(kt + 2, (kt + 2) % NSTAGE);
            cp_wait1();
            __syncthreads();
        } else if (kt + 1 < KT) {
            cp_wait0();
            __syncthreads();
        }
    }

    float al = (mode == 1) ? *alphap : 0.f;
    #pragma unroll
    for (int mt = 0; mt < 4; mt++) {
        #pragma unroll
        for (int rr = 0; rr < 2; rr++) {
            int m = m0 + wm * 64 + mt * 16 + rr * 8 + (lane >> 2);
            float bi = bias[m];
            size_t ybase = ((size_t)b * M + m) * NN + n0;
            #pragma unroll
            for (int nt = 0; nt < 8; nt++) {
                int n = wn * 64 + nt * 8 + (lane & 3) * 2;
                float c0 = acc[mt][nt][rr * 2 + 0] + bi;
                float c1 = acc[mt][nt][rr * 2 + 1] + bi;
                if (mode == 0) {
                    __nv_bfloat162 o = { __float2bfloat16(c0), __float2bfloat16(c1) };
                    *(__nv_bfloat162*)(Yb + ybase + n) = o;
                } else {
                    size_t tbase = ((size_t)b * 256 + m) * NN + n0;
                    float2 t = *(const float2*)(tgt + tbase + n);
                    float2 o = { t.x + al * c0, t.y + al * c1 };
                    *(float2*)(Yf + ybase + n) = o;
                }
            }
        }
    }
}

// ---------------- register-resident softmax on Rq only ------------------------
__global__ __launch_bounds__(256) void softmaxq_k(bf16* __restrict__ TQ)
{
    int tx = threadIdx.x & 31, ty = threadIdx.x >> 5;
    int b = blockIdx.x;
    int n0 = blockIdx.y * 64 + tx * 2;
    size_t base = ((size_t)b * 768 + 256) * NN + n0;
    __shared__ float2 red[8][33];

    uint32_t vals[64];
    float2 mx = { -1e30f, -1e30f };
    #pragma unroll 8
    for (int c = 0; c < 64; c++) {
        __nv_bfloat162 v = *(const __nv_bfloat162*)(TQ + base + (size_t)(ty * 64 + c) * NN);
        vals[c] = *(uint32_t*)&v;
        float2 f = __bfloat1622float2(v);
        mx.x = fmaxf(mx.x, f.x); mx.y = fmaxf(mx.y, f.y);
    }
    red[ty][tx] = mx;
    __syncthreads();
    float2 m = red[0][tx];
    #pragma unroll
    for (int g = 1; g < 8; g++) {
        m.x = fmaxf(m.x, red[g][tx].x);
        m.y = fmaxf(m.y, red[g][tx].y);
    }
    __syncthreads();

    float2 sum = { 0.f, 0.f };
    #pragma unroll 8
    for (int c = 0; c < 64; c++) {
        float2 f = __bfloat1622float2(*(__nv_bfloat162*)&vals[c]);
        float e0 = __expf(f.x - m.x), e1 = __expf(f.y - m.y);
        sum.x += e0; sum.y += e1;
        __nv_bfloat162 e = __floats2bfloat162_rn(e0, e1);
        vals[c] = *(uint32_t*)&e;
    }
    red[ty][tx] = sum;
    __syncthreads();
    float2 s = red[0][tx];
    #pragma unroll
    for (int g = 1; g < 8; g++) { s.x += red[g][tx].x; s.y += red[g][tx].y; }
    float2 inv = { 1.f / s.x, 1.f / s.y };

    #pragma unroll 8
    for (int c = 0; c < 64; c++) {
        float2 f = __bfloat1622float2(*(__nv_bfloat162*)&vals[c]);
        *(__nv_bfloat162*)(TQ + base + (size_t)(ty * 64 + c) * NN) =
            __floats2bfloat162_rn(f.x * inv.x, f.y * inv.y);
    }
}

// ---------------- read-only column sum of exp(Rk raw) -> 1/S ------------------
__global__ __launch_bounds__(256) void colsumk_k(const bf16* __restrict__ SKV,
                                                 float* __restrict__ invSk)
{
    int tx = threadIdx.x & 31, ty = threadIdx.x >> 5;
    int b = blockIdx.x;
    int n0 = blockIdx.y * 64 + tx * 2;
    size_t base = ((size_t)b * 1024 + 512) * NN + n0;
    __shared__ float2 red[8][33];

    float2 sum = { 0.f, 0.f };
    #pragma unroll 8
    for (int c = 0; c < 64; c++) {
        __nv_bfloat162 v = *(const __nv_bfloat162*)(SKV + base + (size_t)(ty * 64 + c) * NN);
        float2 f = __bfloat1622float2(v);
        sum.x += __expf(f.x); sum.y += __expf(f.y);
    }
    red[ty][tx] = sum;
    __syncthreads();
    if (ty == 0) {
        float2 s = red[0][tx];
        #pragma unroll
        for (int g = 1; g < 8; g++) { s.x += red[g][tx].x; s.y += red[g][tx].y; }
        float2 iv = { 1.f / s.x, 1.f / s.y };
        *(float2*)(invSk + (size_t)b * NN + n0) = iv;
    }
}

// ---------------- tensor-core outer reduce ------------------------------------
// ES=0: R via cp.async (already normalized).  ES=1: R = exp(raw)*invS on the fly.
template<int MR, int ES>
__global__ __launch_bounds__(256) void outer_mma_k(
    const bf16* __restrict__ A, int aStride, int aH,
    const bf16* __restrict__ Rm, int rStride, int rOff,
    const float* __restrict__ invSb, float* __restrict__ out)
{
    constexpr int AROWS = MR * 16;
    __shared__ bf16 sA[AROWS * 72];
    __shared__ bf16 sR[64 * 72];
    int bh = blockIdx.x, b = bh >> 3, h = bh & 7;
    const bf16* Ab = A  + ((size_t)b * aStride + h * aH) * NN;
    const bf16* Rb = Rm + ((size_t)b * rStride + rOff + h * 64) * NN;
    const float* iS = ES ? (invSb + (size_t)b * NN) : nullptr;
    float* ob = out + (size_t)bh * (AROWS * 64);
    int tid = threadIdx.x, warp = tid >> 5, lane = tid & 31;

    float acc[MR][4];
    #pragma unroll
    for (int i = 0; i < MR; i++)
        #pragma unroll
        for (int j = 0; j < 4; j++) acc[i][j] = 0.f;

    int kbase = blockIdx.y * 1024;
    for (int kb = 0; kb < 16; kb++) {
        int k0 = kbase + kb * 64;
        #pragma unroll
        for (int c = tid; c < AROWS * 8; c += 256) {
            int r = c >> 3, cc = (c & 7) * 8;
            cpasync16(s2u(&sA[r * 72 + cc]), Ab + (size_t)r * NN + k0 + cc);
        }
        if (!ES) {
            #pragma unroll
            for (int c = tid; c < 512; c += 256) {
                int r = c >> 3, cc = (c & 7) * 8;
                cpasync16(s2u(&sR[r * 72 + cc]), Rb + (size_t)r * NN + k0 + cc);
            }
            cp_commit(); cp_wait0();
        } else {
            cp_commit();
            #pragma unroll
            for (int c = tid; c < 512; c += 256) {
                int r = c >> 3, cc = (c & 7) * 8;
                uint4 ev = *(const uint4*)(Rb + (size_t)r * NN + k0 + cc);
                float4 s0 = *(const float4*)(iS + k0 + cc);
                float4 s1 = *(const float4*)(iS + k0 + cc + 4);
                __nv_bfloat162* ep = (__nv_bfloat162*)&ev;
                float2 f0 = __bfloat1622float2(ep[0]);
                float2 f1 = __bfloat1622float2(ep[1]);
                float2 f2 = __bfloat1622float2(ep[2]);
                float2 f3 = __bfloat1622float2(ep[3]);
                __nv_bfloat162 o[4];
                o[0] = __floats2bfloat162_rn(__expf(f0.x) * s0.x, __expf(f0.y) * s0.y);
                o[1] = __floats2bfloat162_rn(__expf(f1.x) * s0.z, __expf(f1.y) * s0.w);
                o[2] = __floats2bfloat162_rn(__expf(f2.x) * s1.x, __expf(f2.y) * s1.y);
                o[3] = __floats2bfloat162_rn(__expf(f3.x) * s1.z, __expf(f3.y) * s1.w);
                *(uint4*)&sR[r * 72 + cc] = *(uint4*)o;
            }
            cp_wait0();
        }
        __syncthreads();

        int r0 = warp * 8;
        #pragma unroll
        for (int ks = 0; ks < 4; ks++) {
            uint32_t a[MR][4];
            #pragma unroll
            for (int mt = 0; mt < MR; mt++)
                ldsm4(a[mt][0], a[mt][1], a[mt][2], a[mt][3],
                      s2u(&sA[(mt * 16 + (lane & 15)) * 72 + ks * 16 + (lane >> 4) * 8]));
            uint32_t b0, b1;
            {
                int j = lane & 7, half = (lane >> 3) & 1;
                ldsm2(b0, b1, s2u(&sR[(r0 + j) * 72 + ks * 16 + half * 8]));
            }
            #pragma unroll
            for (int mt = 0; mt < MR; mt++)
                mma16816(acc[mt], a[mt], b0, b1);
        }
        __syncthreads();
    }

    int row = lane >> 2, col = warp * 8 + (lane & 3) * 2;
    #pragma unroll
    for (int mt = 0; mt < MR; mt++) {
        atomicAdd(&ob[(mt * 16 + row)     * 64 + col],     acc[mt][0]);
        atomicAdd(&ob[(mt * 16 + row)     * 64 + col + 1], acc[mt][1]);
        atomicAdd(&ob[(mt * 16 + row + 8) * 64 + col],     acc[mt][2]);
        atomicAdd(&ob[(mt * 16 + row + 8) * 64 + col + 1], acc[mt][3]);
    }
}

// ---------------- tiny attention per (b,h) ------------------------------------
__global__ __launch_bounds__(64) void attn_k(
    const float* __restrict__ qr, const float* __restrict__ krvr,
    float* __restrict__ vals)
{
    int bh = blockIdx.x; int t = threadIdx.x;
    __shared__ float sq[2048], sk[2048], sv[2048];
    const float* pq = qr   + (size_t)bh * 2048;
    const float* pk = krvr + (size_t)bh * 4096;
    const float* pv = pk + 2048;
    for (int i = t; i < 2048; i += 64) { sq[i] = pq[i]; sk[i] = pk[i]; sv[i] = pv[i]; }
    __syncthreads();

    float sc[64];
    #pragma unroll 4
    for (int k = 0; k < 64; k++) {
        float s = 0.f;
        #pragma unroll
        for (int d = 0; d < 32; d++) s += sq[d * 64 + t] * sk[d * 64 + k];
        sc[k] = s * 0.17677669529663687f;
    }
    float m = -1e30f;
    #pragma unroll
    for (int k = 0; k < 64; k++) m = fmaxf(m, sc[k]);
    float s = 0.f;
    #pragma unroll
    for (int k = 0; k < 64; k++) { sc[k] = __expf(sc[k] - m); s += sc[k]; }
    float inv = 1.f / s;
    #pragma unroll
    for (int k = 0; k < 64; k++) sc[k] *= inv;

    #pragma unroll 4
    for (int d = 0; d < 32; d++) {
        float v = 0.f;
        #pragma unroll
        for (int k = 0; k < 64; k++) v += sv[d * 64 + k] * sc[k];
        vals[(size_t)bh * 2048 + d * 64 + t] = v;
    }
}

// ---------------- U[b][m][h*64+r] = sum_d Wout[m][h*32+d] * vals[bh][d][r] ----
__global__ __launch_bounds__(256) void u_k(
    const float* __restrict__ Wout, const float* __restrict__ vals,
    bf16* __restrict__ U)
{
    int bh = blockIdx.x, b = bh >> 3, h = bh & 7;
    int m = threadIdx.x;
    __shared__ float vs[2048];
    const float* pv = vals + (size_t)bh * 2048;
    for (int i = threadIdx.x; i < 2048; i += 256) vs[i] = pv[i];
    __syncthreads();

    float acc[64];
    #pragma unroll
    for (int r = 0; r < 64; r++) acc[r] = 0.f;
    #pragma unroll 4
    for (int d = 0; d < 32; d++) {
        float w = Wout[(size_t)m * 256 + h * 32 + d];
        #pragma unroll
        for (int r = 0; r < 64; r++) acc[r] += w * vs[d * 64 + r];
    }
    bf16* up = U + ((size_t)b * 256 + m) * 512 + h * 64;
    #pragma unroll
    for (int r = 0; r < 32; r++) {
        __nv_bfloat162 o = { __float2bfloat16(acc[r * 2]), __float2bfloat16(acc[r * 2 + 1]) };
        *(__nv_bfloat162*)(up + r * 2) = o;
    }
}

// ------------------------------ launcher --------------------------------------
extern "C" void kernel_launch(void* const* d_in, const int* in_sizes, int n_in,
                              void* d_out, int out_size)
{
    const float* src   = (const float*)d_in[0];
    const float* tgt   = (const float*)d_in[1];
    const float* Wq    = (const float*)d_in[2];
    const float* bq    = (const float*)d_in[3];
    const float* Wkv   = (const float*)d_in[4];
    const float* bkv   = (const float*)d_in[5];
    const float* Wrq   = (const float*)d_in[6];
    const float* brq   = (const float*)d_in[7];
    const float* Wrk   = (const float*)d_in[8];
    const float* brk   = (const float*)d_in[9];
    const float* Wout  = (const float*)d_in[10];
    const float* bout  = (const float*)d_in[11];
    const float* alpha = (const float*)d_in[12];
    float* out = (float*)d_out;

    bf16 *ptq, *pskv, *psrcb, *ptgtb, *pWtgt, *pWsrc, *pU;
    float *pbtgt, *pbsrc, *piSk, *pqr, *pkrvr, *pvals;
    cudaGetSymbolAddress((void**)&ptq,   g_tq);
    cudaGetSymbolAddress((void**)&pskv,  g_skv);
    cudaGetSymbolAddress((void**)&psrcb, g_srcb);
    cudaGetSymbolAddress((void**)&ptgtb, g_tgtb);
    cudaGetSymbolAddress((void**)&pWtgt, g_Wtgt);
    cudaGetSymbolAddress((void**)&pWsrc, g_Wsrc);
    cudaGetSymbolAddress((void**)&pbtgt, g_btgt);
    cudaGetSymbolAddress((void**)&pbsrc, g_bsrc);
    cudaGetSymbolAddress((void**)&piSk,  g_iSk);
    cudaGetSymbolAddress((void**)&pU,    g_U);
    cudaGetSymbolAddress((void**)&pqr,   g_qr);
    cudaGetSymbolAddress((void**)&pkrvr, g_krvr);
    cudaGetSymbolAddress((void**)&pvals, g_vals);

    cudaFuncSetAttribute(hgemm_k, cudaFuncAttributeMaxDynamicSharedMemorySize, HSMEM_BYTES);

    {
        int blocks = (int)((PREP_TOTAL + 255) / 256);
        prep_k<<<blocks, 256>>>(src, tgt, Wq, Wkv, Wrq, Wrk, bq, bkv, brq, brk,
                                psrcb, ptgtb, pWtgt, pWsrc, pbtgt, pbsrc, pqr, pkrvr);
    }

    // fused projections: src -> [kv;Rk_raw] (M=1024), tgt -> [q;Rq_raw] (M=768)
    hgemm_k<<<dim3(NN / 128, 8, BB), 128, HSMEM_BYTES>>>(
        pWsrc, pbsrc, psrcb, 256, pskv, nullptr, 1024, 256, 0, 0, nullptr, nullptr);
    hgemm_k<<<dim3(NN / 128, 6, BB), 128, HSMEM_BYTES>>>(
        pWtgt, pbtgt, ptgtb, 256, ptq, nullptr, 768, 256, 0, 0, nullptr, nullptr);

    // Rq: in-place softmax (needed materialized by final GEMM)
    softmaxq_k<<<dim3(BB, NN / 64), 256>>>(ptq);
    // Rk: read-only column sums -> 1/S (softmax applied on the fly in outer<4>)
    colsumk_k<<<dim3(BB, NN / 64), 256>>>(pskv, piSk);

    outer_mma_k<2, 0><<<dim3(64, 9), 256>>>(ptq,  768,  32, ptq,  768,  256, nullptr, pqr);
    outer_mma_k<4, 1><<<dim3(64, 9), 256>>>(pskv, 1024, 64, pskv, 1024, 512, piSk, pkrvr);

    attn_k<<<64, 64>>>(pqr, pkrvr, pvals);

    u_k<<<64, 256>>>(Wout, pvals, pU);

    // out = tgt + alpha * (U @ Rq + bout)
    hgemm_k<<<dim3(NN / 128, 2, BB), 128, HSMEM_BYTES>>>(
        pU, bout, ptq + (size_t)256 * NN, 768, nullptr, out, 256, 512, 1, 1, tgt, alpha);
}